// round 6
// baseline (speedup 1.0000x reference)
#include <cuda_runtime.h>
#include <cuda_fp16.h>
#include <cstdint>

// ============================================================================
// SimpleRNN fused kernel: fp16 mma.sync, M=64/CTA, 2 CTAs/SM.
// R6: intra-warp overlap — warp tile split into two N-halves; half1's MMA
// k-loop is interleaved with half0's tanh/pack/store so MUFU runs under HMMA.
//   h_{t+1} = tanh(x_t@W_ih^T + b + h_t@W_hh^T), t=0..27; out = h@W_fc^T + b_fc
// ============================================================================

#define SM_WHH 0          // 128 x 128 fp16, row stride 256B, swz ^(row&7)
#define SM_WIH 32768      // 128 x 32 fp16, row stride 64B, swz ^(row&3)
#define SM_H0  40960      // 64 x 128 fp16 ping
#define SM_H1  57344      // pong
#define SM_X0  73728      // 64 x 32 fp16 (col28 = bias 1.0) ping
#define SM_X1  77824      // pong
#define SM_WFC 81920      // 10 x 128 fp32
#define SM_BFC 87040      // 10 fp32
#define SM_TOTAL 87168
// post-loop alias: fp32 h28 at offset 0, stride 132 floats

static __device__ __forceinline__ uint32_t s2u(const void* p) {
    uint32_t a;
    asm("{ .reg .u64 t; cvta.to.shared.u64 t, %1; cvt.u32.u64 %0, t; }"
        : "=r"(a) : "l"(p));
    return a;
}

static __device__ __forceinline__ uint32_t packh(float v0, float v1) {
    uint32_t r;
    asm("cvt.rn.f16x2.f32 %0, %1, %2;" : "=r"(r) : "f"(v1), "f"(v0));
    return r;
}

// accurate tanh: 1 - 2/(e^{2x}+1)  (~1e-7 abs err)
static __device__ __forceinline__ float tanh_acc(float v) {
    float a = fminf(fmaxf(v * 2.885390082f, -30.0f), 30.0f);
    float e; asm("ex2.approx.f32 %0, %1;" : "=f"(e) : "f"(a));
    float r; asm("rcp.approx.f32 %0, %1;" : "=f"(r) : "f"(e + 1.0f));
    return fmaf(-2.0f, r, 1.0f);
}

#define LDSM4(R, A)                                                              \
    asm volatile("ldmatrix.sync.aligned.m8n8.x4.shared.b16 {%0,%1,%2,%3}, [%4];" \
                 : "=r"((R)[0]), "=r"((R)[1]), "=r"((R)[2]), "=r"((R)[3])        \
                 : "r"(A))

static __device__ __forceinline__ void mma_f16(float* d, const uint32_t* a,
                                               uint32_t b0, uint32_t b1) {
    asm volatile(
        "mma.sync.aligned.m16n8k16.row.col.f32.f16.f16.f32 "
        "{%0,%1,%2,%3}, {%4,%5,%6,%7}, {%8,%9}, {%0,%1,%2,%3};"
        : "+f"(d[0]), "+f"(d[1]), "+f"(d[2]), "+f"(d[3])
        : "r"(a[0]), "r"(a[1]), "r"(a[2]), "r"(a[3]), "r"(b0), "r"(b1));
}

__global__ void __launch_bounds__(256, 2) SimpleRNN_fused_kernel(
    const float* __restrict__ x,    // [16384,1,28,28]
    const float* __restrict__ Wih,  // [128,28]
    const float* __restrict__ Whh,  // [128,128]
    const float* __restrict__ bih,  // [128]
    const float* __restrict__ bhh,  // [128]
    const float* __restrict__ Wfc,  // [10,128]
    const float* __restrict__ bfc,  // [10]
    float* __restrict__ out)        // [16384,10]
{
    extern __shared__ char smem[];
    const uint32_t sb = s2u(smem);
    const int tid  = threadIdx.x;
    const int lane = tid & 31;
    const int wid  = tid >> 5;
    const int m0 = (wid & 1) * 32;   // warp M offset
    const int n0 = (wid >> 1) * 32;  // warp N offset

    const int rowA = lane & 15;
    const int csA  = lane >> 4;
    const int rowB = ((lane >> 4) << 3) | (lane & 7);
    const int csB  = (lane >> 3) & 1;
    const int l7 = lane & 7, l3 = lane & 3;

    // ---- one-time: weights -> fp16 swizzled SMEM ----
    for (int i = tid; i < 128 * 128; i += 256) {
        int n = i >> 7, k = i & 127;
        uint32_t byte = (uint32_t)(n * 256 + (((k >> 3) ^ (n & 7)) << 4) + (k & 7) * 2);
        *(uint16_t*)(smem + SM_WHH + byte) = __half_as_ushort(__float2half_rn(Whh[i]));
    }
    for (int i = tid; i < 128 * 32; i += 256) {
        int n = i >> 5, k = i & 31;
        float v = (k < 28) ? Wih[n * 28 + k] : ((k == 28) ? (bih[n] + bhh[n]) : 0.0f);
        uint32_t byte = (uint32_t)(n * 64 + (((k >> 3) ^ (n & 3)) << 4) + (k & 7) * 2);
        *(uint16_t*)(smem + SM_WIH + byte) = __half_as_ushort(__float2half_rn(v));
    }
    for (int i = tid; i < 1280; i += 256) ((float*)(smem + SM_WFC))[i] = Wfc[i];
    if (tid < 10) ((float*)(smem + SM_BFC))[tid] = bfc[tid];

    // ---- x: row r = tid>>2 (0..63), col chunk q = tid&3 ----
    const int xr = tid >> 2, xq = tid & 3;
    const size_t xbase = ((size_t)blockIdx.x * 64 + xr) * 784 + (size_t)xq * 8;
    const uint32_t xoff = (uint32_t)(xr * 64 + ((xq ^ (xr & 3)) << 4));
    float xf[8];
    {
        const float4* px = (const float4*)(x + xbase);
        float4 v0 = px[0];
        xf[0]=v0.x; xf[1]=v0.y; xf[2]=v0.z; xf[3]=v0.w;
        if (xq < 3) { float4 v1 = px[1]; xf[4]=v1.x; xf[5]=v1.y; xf[6]=v1.z; xf[7]=v1.w; }
    }
    {
        uint32_t p0 = packh(xf[0], xf[1]), p1 = packh(xf[2], xf[3]);
        uint32_t p2, p3;
        if (xq < 3) { p2 = packh(xf[4], xf[5]); p3 = packh(xf[6], xf[7]); }
        else        { p2 = 0x00003C00u; p3 = 0u; }
        asm volatile("st.shared.v4.b32 [%0], {%1,%2,%3,%4};"
                     :: "r"(sb + SM_X0 + xoff), "r"(p0), "r"(p1), "r"(p2), "r"(p3) : "memory");
    }
    __syncthreads();

    float acc[2][4][4];

    // tanh+pack+store one (mt,nt) accumulator group into Hwr
    #define GROUP_STORE(Hwr, mt, nt)                                              \
        do {                                                                      \
            const float* c = acc[mt][nt];                                         \
            int r0_ = m0 + (mt) * 16 + (lane >> 2);                               \
            int r1_ = r0_ + 8;                                                    \
            int ch_ = (n0 >> 3) + (nt);                                           \
            uint32_t b0_ = (uint32_t)(r0_ * 256 + ((ch_ ^ (r0_ & 7)) << 4) + (lane & 3) * 4); \
            uint32_t b1_ = (uint32_t)(r1_ * 256 + ((ch_ ^ (r1_ & 7)) << 4) + (lane & 3) * 4); \
            *(uint32_t*)(smem + (Hwr) + b0_) = packh(tanh_acc(c[0]), tanh_acc(c[1])); \
            *(uint32_t*)(smem + (Hwr) + b1_) = packh(tanh_acc(c[2]), tanh_acc(c[3])); \
        } while (0)

    // 4 MMAs for one k-chunk of one N-half (nt base = 0 or 2)
    #define MMA4(A, Bf, ntb)                                                      \
        do {                                                                      \
            mma_f16(acc[0][(ntb)],     A[0], Bf[0], Bf[1]);                       \
            mma_f16(acc[0][(ntb) + 1], A[0], Bf[2], Bf[3]);                       \
            mma_f16(acc[1][(ntb)],     A[1], Bf[0], Bf[1]);                       \
            mma_f16(acc[1][(ntb) + 1], A[1], Bf[2], Bf[3]);                       \
        } while (0)

    // load A pair + B frag for x GEMM (buffer Xrd, weight WIH)
    #define LDX(A, Bf, kt, nhalf, Xrd)                                            \
        do {                                                                      \
            LDSM4(A[0], sb + (Xrd) + (uint32_t)((m0 + rowA) * 64 + ((((kt)*2 + csA) ^ l3) << 4))); \
            LDSM4(A[1], sb + (Xrd) + (uint32_t)((m0 + 16 + rowA) * 64 + ((((kt)*2 + csA) ^ l3) << 4))); \
            LDSM4(Bf, sb + SM_WIH + (uint32_t)((n0 + (nhalf)*16 + rowB) * 64 + ((((kt)*2 + csB) ^ l3) << 4))); \
        } while (0)

    // load A pair + B frag for hh GEMM (buffer Hrd, weight WHH)
    #define LDH(A, Bf, kt, nhalf, Hrd)                                            \
        do {                                                                      \
            LDSM4(A[0], sb + (Hrd) + (uint32_t)((m0 + rowA) * 256 + ((((kt)*2 + csA) ^ l7) << 4))); \
            LDSM4(A[1], sb + (Hrd) + (uint32_t)((m0 + 16 + rowA) * 256 + ((((kt)*2 + csA) ^ l7) << 4))); \
            LDSM4(Bf, sb + SM_WHH + (uint32_t)((n0 + (nhalf)*16 + rowB) * 256 + ((((kt)*2 + csB) ^ l7) << 4))); \
        } while (0)

    #pragma unroll 1
    for (int t = 0; t < 28; t++) {
        const uint32_t Hrd = (t & 1) ? SM_H1 : SM_H0;
        const uint32_t Hwr = (t & 1) ? SM_H0 : SM_H1;
        const uint32_t Xrd = (t & 1) ? SM_X1 : SM_X0;
        const uint32_t Xwr = (t & 1) ? SM_X0 : SM_X1;

        #pragma unroll
        for (int mt = 0; mt < 2; mt++)
            #pragma unroll
            for (int nt = 0; nt < 4; nt++)
                #pragma unroll
                for (int j = 0; j < 4; j++) acc[mt][nt][j] = 0.0f;

        uint32_t A[2][4], Bf[4];

        // ================= Phase 1: all MMAs for N-half0 (acc nt 0,1) ========
        #pragma unroll
        for (int kt = 0; kt < 2; kt++) { LDX(A, Bf, kt, 0, Xrd); MMA4(A, Bf, 0); }
        if (t > 0) {
            #pragma unroll
            for (int kt = 0; kt < 8; kt++) { LDH(A, Bf, kt, 0, Hrd); MMA4(A, Bf, 0); }
        }

        // issue x(t+1) global loads early (consumed in phase 3)
        if (t < 27) {
            const float4* px = (const float4*)(x + xbase + (size_t)(t + 1) * 28);
            float4 v0 = px[0];
            xf[0]=v0.x; xf[1]=v0.y; xf[2]=v0.z; xf[3]=v0.w;
            if (xq < 3) { float4 v1 = px[1]; xf[4]=v1.x; xf[5]=v1.y; xf[6]=v1.z; xf[7]=v1.w; }
        }

        // ============ Phase 2: N-half1 MMAs interleaved with half0 tanh ======
        #pragma unroll
        for (int kt = 0; kt < 2; kt++) { LDX(A, Bf, kt, 1, Xrd); MMA4(A, Bf, 2); }

        if (t > 0 && t < 27) {
            #pragma unroll
            for (int kt = 0; kt < 8; kt++) {
                LDH(A, Bf, kt, 1, Hrd);
                MMA4(A, Bf, 2);
                // interleave half0 epilogue: one group per two k-chunks
                if (kt == 1) GROUP_STORE(Hwr, 0, 0);
                if (kt == 3) GROUP_STORE(Hwr, 0, 1);
                if (kt == 5) GROUP_STORE(Hwr, 1, 0);
                if (kt == 7) GROUP_STORE(Hwr, 1, 1);
            }
        } else if (t > 0) {  // t == 27: MMAs only, epilogue handled below
            #pragma unroll
            for (int kt = 0; kt < 8; kt++) { LDH(A, Bf, kt, 1, Hrd); MMA4(A, Bf, 2); }
        }

        if (t < 27) {
            if (t == 0) {  // no hh loop to hide under; do half0 groups now
                GROUP_STORE(Hwr, 0, 0); GROUP_STORE(Hwr, 0, 1);
                GROUP_STORE(Hwr, 1, 0); GROUP_STORE(Hwr, 1, 1);
            }
            // ============ Phase 3: half1 epilogue + x(t+1) store =============
            GROUP_STORE(Hwr, 0, 2); GROUP_STORE(Hwr, 0, 3);
            GROUP_STORE(Hwr, 1, 2); GROUP_STORE(Hwr, 1, 3);

            uint32_t p0 = packh(xf[0], xf[1]), p1 = packh(xf[2], xf[3]);
            uint32_t p2, p3;
            if (xq < 3) { p2 = packh(xf[4], xf[5]); p3 = packh(xf[6], xf[7]); }
            else        { p2 = 0x00003C00u; p3 = 0u; }
            asm volatile("st.shared.v4.b32 [%0], {%1,%2,%3,%4};"
                         :: "r"(sb + Xwr + xoff), "r"(p0), "r"(p1), "r"(p2), "r"(p3) : "memory");
        } else {
            // final step: fp32 h28 over dead W_hh region; barrier first
            __syncthreads();
            float* h32 = (float*)smem;
            #pragma unroll
            for (int mt = 0; mt < 2; mt++)
                #pragma unroll
                for (int nt = 0; nt < 4; nt++) {
                    const float* c = acc[mt][nt];
                    int r0 = m0 + mt * 16 + (lane >> 2);
                    int col = n0 + nt * 8 + (lane & 3) * 2;
                    *(float2*)(h32 + r0 * 132 + col)       = make_float2(tanh_acc(c[0]), tanh_acc(c[1]));
                    *(float2*)(h32 + (r0 + 8) * 132 + col) = make_float2(tanh_acc(c[2]), tanh_acc(c[3]));
                }
        }
        __syncthreads();
    }

    // ---- fc: out = h28 @ W_fc^T + b_fc (fp32 SIMT, 128 threads) ----
    if (tid < 128) {
        const float* h32  = (const float*)smem;
        const float* wfc  = (const float*)(smem + SM_WFC);
        const float* bfcS = (const float*)(smem + SM_BFC);
        int r = tid >> 1;
        int c0 = (tid & 1) * 5;
        float s[5];
        #pragma unroll
        for (int j = 0; j < 5; j++) s[j] = bfcS[c0 + j];
        const float4* hr = (const float4*)(h32 + r * 132);
        #pragma unroll 8
        for (int k4 = 0; k4 < 32; k4++) {
            float4 hv = hr[k4];
            #pragma unroll
            for (int j = 0; j < 5; j++) {
                float4 wv = ((const float4*)(wfc + (c0 + j) * 128))[k4];
                s[j] += hv.x * wv.x + hv.y * wv.y + hv.z * wv.z + hv.w * wv.w;
            }
        }
        float* o = out + ((size_t)blockIdx.x * 64 + r) * 10 + c0;
        #pragma unroll
        for (int j = 0; j < 5; j++) o[j] = s[j];
    }
}

extern "C" void kernel_launch(void* const* d_in, const int* in_sizes, int n_in,
                              void* d_out, int out_size) {
    const float* x   = (const float*)d_in[0];
    const float* Wih = (const float*)d_in[1];
    const float* Whh = (const float*)d_in[2];
    const float* bih = (const float*)d_in[3];
    const float* bhh = (const float*)d_in[4];
    const float* Wfc = (const float*)d_in[5];
    const float* bfc = (const float*)d_in[6];
    float* out = (float*)d_out;

    cudaFuncSetAttribute(SimpleRNN_fused_kernel,
                         cudaFuncAttributeMaxDynamicSharedMemorySize, SM_TOTAL);
    SimpleRNN_fused_kernel<<<256, 256, SM_TOTAL>>>(x, Wih, Whh, bih, bhh, Wfc, bfc, out);
}

// round 7
// speedup vs baseline: 1.4618x; 1.4618x over previous
#include <cuda_runtime.h>
#include <cuda_fp16.h>
#include <cstdint>

// ============================================================================
// SimpleRNN fused kernel: fp16 mma.sync, M=64/CTA, 2 CTAs/SM (R5 structure).
// R7: tanh.approx.f32 epilogue (1 MUFU/value, no FMA chain) + W_ih B-frags
// cached in registers across all timesteps.
//   h_{t+1} = tanh(x_t@W_ih^T + b + h_t@W_hh^T), t=0..27; out = h@W_fc^T + b_fc
// ============================================================================

#define SM_WHH 0          // 128 x 128 fp16, row stride 256B, swz ^(row&7)
#define SM_WIH 32768      // 128 x 32 fp16, row stride 64B, swz ^(row&3)
#define SM_H0  40960      // 64 x 128 fp16 ping
#define SM_H1  57344      // pong
#define SM_X0  73728      // 64 x 32 fp16 (col28 = bias 1.0) ping
#define SM_X1  77824      // pong
#define SM_WFC 81920      // 10 x 128 fp32
#define SM_BFC 87040      // 10 fp32
#define SM_TOTAL 87168
// post-loop alias: fp32 h28 at offset 0, stride 132 floats

static __device__ __forceinline__ uint32_t s2u(const void* p) {
    uint32_t a;
    asm("{ .reg .u64 t; cvta.to.shared.u64 t, %1; cvt.u32.u64 %0, t; }"
        : "=r"(a) : "l"(p));
    return a;
}

static __device__ __forceinline__ uint32_t packh(float v0, float v1) {
    uint32_t r;
    asm("cvt.rn.f16x2.f32 %0, %1, %2;" : "=r"(r) : "f"(v1), "f"(v0));
    return r;
}

// fast tanh: single MUFU op (max abs err ~2^-10.66, same order as fp16 quant)
static __device__ __forceinline__ float tanh_fast(float v) {
    float r;
    asm("tanh.approx.f32 %0, %1;" : "=f"(r) : "f"(v));
    return r;
}

// accurate tanh for the final step (feeds fc directly; keep it clean)
static __device__ __forceinline__ float tanh_acc(float v) {
    float a = fminf(fmaxf(v * 2.885390082f, -30.0f), 30.0f);
    float e; asm("ex2.approx.f32 %0, %1;" : "=f"(e) : "f"(a));
    float r; asm("rcp.approx.f32 %0, %1;" : "=f"(r) : "f"(e + 1.0f));
    return fmaf(-2.0f, r, 1.0f);
}

#define LDSM4(R, A)                                                              \
    asm volatile("ldmatrix.sync.aligned.m8n8.x4.shared.b16 {%0,%1,%2,%3}, [%4];" \
                 : "=r"((R)[0]), "=r"((R)[1]), "=r"((R)[2]), "=r"((R)[3])        \
                 : "r"(A))

static __device__ __forceinline__ void mma_f16(float* d, const uint32_t* a,
                                               uint32_t b0, uint32_t b1) {
    asm volatile(
        "mma.sync.aligned.m16n8k16.row.col.f32.f16.f16.f32 "
        "{%0,%1,%2,%3}, {%4,%5,%6,%7}, {%8,%9}, {%0,%1,%2,%3};"
        : "+f"(d[0]), "+f"(d[1]), "+f"(d[2]), "+f"(d[3])
        : "r"(a[0]), "r"(a[1]), "r"(a[2]), "r"(a[3]), "r"(b0), "r"(b1));
}

__global__ void __launch_bounds__(256, 2) SimpleRNN_fused_kernel(
    const float* __restrict__ x,    // [16384,1,28,28]
    const float* __restrict__ Wih,  // [128,28]
    const float* __restrict__ Whh,  // [128,128]
    const float* __restrict__ bih,  // [128]
    const float* __restrict__ bhh,  // [128]
    const float* __restrict__ Wfc,  // [10,128]
    const float* __restrict__ bfc,  // [10]
    float* __restrict__ out)        // [16384,10]
{
    extern __shared__ char smem[];
    const uint32_t sb = s2u(smem);
    const int tid  = threadIdx.x;
    const int lane = tid & 31;
    const int wid  = tid >> 5;
    const int m0 = (wid & 1) * 32;   // warp M offset
    const int n0 = (wid >> 1) * 32;  // warp N offset

    const int rowA = lane & 15;
    const int csA  = lane >> 4;
    const int rowB = ((lane >> 4) << 3) | (lane & 7);
    const int csB  = (lane >> 3) & 1;
    const int l7 = lane & 7, l3 = lane & 3;

    // ---- one-time: weights -> fp16 swizzled SMEM ----
    for (int i = tid; i < 128 * 128; i += 256) {
        int n = i >> 7, k = i & 127;
        uint32_t byte = (uint32_t)(n * 256 + (((k >> 3) ^ (n & 7)) << 4) + (k & 7) * 2);
        *(uint16_t*)(smem + SM_WHH + byte) = __half_as_ushort(__float2half_rn(Whh[i]));
    }
    for (int i = tid; i < 128 * 32; i += 256) {
        int n = i >> 5, k = i & 31;
        float v = (k < 28) ? Wih[n * 28 + k] : ((k == 28) ? (bih[n] + bhh[n]) : 0.0f);
        uint32_t byte = (uint32_t)(n * 64 + (((k >> 3) ^ (n & 3)) << 4) + (k & 7) * 2);
        *(uint16_t*)(smem + SM_WIH + byte) = __half_as_ushort(__float2half_rn(v));
    }
    for (int i = tid; i < 1280; i += 256) ((float*)(smem + SM_WFC))[i] = Wfc[i];
    if (tid < 10) ((float*)(smem + SM_BFC))[tid] = bfc[tid];

    // ---- x: row r = tid>>2 (0..63), col chunk q = tid&3 ----
    const int xr = tid >> 2, xq = tid & 3;
    const size_t xbase = ((size_t)blockIdx.x * 64 + xr) * 784 + (size_t)xq * 8;
    const uint32_t xoff = (uint32_t)(xr * 64 + ((xq ^ (xr & 3)) << 4));
    float xf[8];
    {
        const float4* px = (const float4*)(x + xbase);
        float4 v0 = px[0];
        xf[0]=v0.x; xf[1]=v0.y; xf[2]=v0.z; xf[3]=v0.w;
        if (xq < 3) { float4 v1 = px[1]; xf[4]=v1.x; xf[5]=v1.y; xf[6]=v1.z; xf[7]=v1.w; }
    }
    {
        uint32_t p0 = packh(xf[0], xf[1]), p1 = packh(xf[2], xf[3]);
        uint32_t p2, p3;
        if (xq < 3) { p2 = packh(xf[4], xf[5]); p3 = packh(xf[6], xf[7]); }
        else        { p2 = 0x00003C00u; p3 = 0u; }  // col28 = 1.0 bias
        asm volatile("st.shared.v4.b32 [%0], {%1,%2,%3,%4};"
                     :: "r"(sb + SM_X0 + xoff), "r"(p0), "r"(p1), "r"(p2), "r"(p3) : "memory");
    }
    __syncthreads();

    // ---- cache W_ih B-fragments in registers (constant across steps) ----
    uint32_t Bih[2][2][4];  // [kt][nt][frag]
    #pragma unroll
    for (int kt = 0; kt < 2; kt++)
        #pragma unroll
        for (int nt = 0; nt < 2; nt++) {
            uint32_t ro = (uint32_t)((n0 + nt * 16 + rowB) * 64 + (((kt * 2 + csB) ^ l3) << 4));
            LDSM4(Bih[kt][nt], sb + SM_WIH + ro);
        }

    float acc[2][4][4];

    #pragma unroll 1
    for (int t = 0; t < 28; t++) {
        const uint32_t Hrd = (t & 1) ? SM_H1 : SM_H0;
        const uint32_t Hwr = (t & 1) ? SM_H0 : SM_H1;
        const uint32_t Xrd = (t & 1) ? SM_X1 : SM_X0;
        const uint32_t Xwr = (t & 1) ? SM_X0 : SM_X1;

        #pragma unroll
        for (int mt = 0; mt < 2; mt++)
            #pragma unroll
            for (int nt = 0; nt < 4; nt++)
                #pragma unroll
                for (int j = 0; j < 4; j++) acc[mt][nt][j] = 0.0f;

        // ---- x GEMM (K=32), B from registers ----
        #pragma unroll
        for (int kt = 0; kt < 2; kt++) {
            uint32_t A[2][4];
            #pragma unroll
            for (int mt = 0; mt < 2; mt++) {
                uint32_t ro = (uint32_t)((m0 + mt * 16 + rowA) * 64 + (((kt * 2 + csA) ^ l3) << 4));
                LDSM4(A[mt], sb + Xrd + ro);
            }
            #pragma unroll
            for (int mt = 0; mt < 2; mt++)
                #pragma unroll
                for (int nt = 0; nt < 2; nt++) {
                    mma_f16(acc[mt][2*nt],   A[mt], Bih[kt][nt][0], Bih[kt][nt][1]);
                    mma_f16(acc[mt][2*nt+1], A[mt], Bih[kt][nt][2], Bih[kt][nt][3]);
                }
        }

        // ---- hh GEMM (K=128), skip at t=0 ----
        if (t > 0) {
            #pragma unroll
            for (int kt = 0; kt < 8; kt++) {
                uint32_t A[2][4], B[2][4];
                #pragma unroll
                for (int mt = 0; mt < 2; mt++) {
                    uint32_t ro = (uint32_t)((m0 + mt * 16 + rowA) * 256 + (((kt * 2 + csA) ^ l7) << 4));
                    LDSM4(A[mt], sb + Hrd + ro);
                }
                #pragma unroll
                for (int nt = 0; nt < 2; nt++) {
                    uint32_t ro = (uint32_t)((n0 + nt * 16 + rowB) * 256 + (((kt * 2 + csB) ^ l7) << 4));
                    LDSM4(B[nt], sb + SM_WHH + ro);
                }
                #pragma unroll
                for (int mt = 0; mt < 2; mt++)
                    #pragma unroll
                    for (int nt = 0; nt < 2; nt++) {
                        mma_f16(acc[mt][2*nt],   A[mt], B[nt][0], B[nt][1]);
                        mma_f16(acc[mt][2*nt+1], A[mt], B[nt][2], B[nt][3]);
                    }
            }
        }

        if (t < 27) {
            // prefetch x(t+1)
            const float4* px = (const float4*)(x + xbase + (size_t)(t + 1) * 28);
            float4 v0 = px[0];
            xf[0]=v0.x; xf[1]=v0.y; xf[2]=v0.z; xf[3]=v0.w;
            if (xq < 3) { float4 v1 = px[1]; xf[4]=v1.x; xf[5]=v1.y; xf[6]=v1.z; xf[7]=v1.w; }

            // h(t+1) = tanh.approx(acc) -> fp16 into Hwr
            #pragma unroll
            for (int mt = 0; mt < 2; mt++)
                #pragma unroll
                for (int nt = 0; nt < 4; nt++) {
                    const float* c = acc[mt][nt];
                    int r0 = m0 + mt * 16 + (lane >> 2);
                    int r1 = r0 + 8;
                    int chunk = (n0 >> 3) + nt;
                    uint32_t b0 = (uint32_t)(r0 * 256 + ((chunk ^ (r0 & 7)) << 4) + (lane & 3) * 4);
                    uint32_t b1 = (uint32_t)(r1 * 256 + ((chunk ^ (r1 & 7)) << 4) + (lane & 3) * 4);
                    *(uint32_t*)(smem + Hwr + b0) = packh(tanh_fast(c[0]), tanh_fast(c[1]));
                    *(uint32_t*)(smem + Hwr + b1) = packh(tanh_fast(c[2]), tanh_fast(c[3]));
                }
            // store x(t+1) into Xwr
            uint32_t p0 = packh(xf[0], xf[1]), p1 = packh(xf[2], xf[3]);
            uint32_t p2, p3;
            if (xq < 3) { p2 = packh(xf[4], xf[5]); p3 = packh(xf[6], xf[7]); }
            else        { p2 = 0x00003C00u; p3 = 0u; }
            asm volatile("st.shared.v4.b32 [%0], {%1,%2,%3,%4};"
                         :: "r"(sb + Xwr + xoff), "r"(p0), "r"(p1), "r"(p2), "r"(p3) : "memory");
        } else {
            // final step: accurate tanh, fp32 h28 over dead W_hh; barrier first
            __syncthreads();
            float* h32 = (float*)smem;
            #pragma unroll
            for (int mt = 0; mt < 2; mt++)
                #pragma unroll
                for (int nt = 0; nt < 4; nt++) {
                    const float* c = acc[mt][nt];
                    int r0 = m0 + mt * 16 + (lane >> 2);
                    int col = n0 + nt * 8 + (lane & 3) * 2;
                    *(float2*)(h32 + r0 * 132 + col)       = make_float2(tanh_acc(c[0]), tanh_acc(c[1]));
                    *(float2*)(h32 + (r0 + 8) * 132 + col) = make_float2(tanh_acc(c[2]), tanh_acc(c[3]));
                }
        }
        __syncthreads();
    }

    // ---- fc: out = h28 @ W_fc^T + b_fc (fp32 SIMT, 128 threads) ----
    if (tid < 128) {
        const float* h32  = (const float*)smem;
        const float* wfc  = (const float*)(smem + SM_WFC);
        const float* bfcS = (const float*)(smem + SM_BFC);
        int r = tid >> 1;
        int c0 = (tid & 1) * 5;
        float s[5];
        #pragma unroll
        for (int j = 0; j < 5; j++) s[j] = bfcS[c0 + j];
        const float4* hr = (const float4*)(h32 + r * 132);
        #pragma unroll 8
        for (int k4 = 0; k4 < 32; k4++) {
            float4 hv = hr[k4];
            #pragma unroll
            for (int j = 0; j < 5; j++) {
                float4 wv = ((const float4*)(wfc + (c0 + j) * 128))[k4];
                s[j] += hv.x * wv.x + hv.y * wv.y + hv.z * wv.z + hv.w * wv.w;
            }
        }
        float* o = out + ((size_t)blockIdx.x * 64 + r) * 10 + c0;
        #pragma unroll
        for (int j = 0; j < 5; j++) o[j] = s[j];
    }
}

extern "C" void kernel_launch(void* const* d_in, const int* in_sizes, int n_in,
                              void* d_out, int out_size) {
    const float* x   = (const float*)d_in[0];
    const float* Wih = (const float*)d_in[1];
    const float* Whh = (const float*)d_in[2];
    const float* bih = (const float*)d_in[3];
    const float* bhh = (const float*)d_in[4];
    const float* Wfc = (const float*)d_in[5];
    const float* bfc = (const float*)d_in[6];
    float* out = (float*)d_out;

    cudaFuncSetAttribute(SimpleRNN_fused_kernel,
                         cudaFuncAttributeMaxDynamicSharedMemorySize, SM_TOTAL);
    SimpleRNN_fused_kernel<<<256, 256, SM_TOTAL>>>(x, Wih, Whh, bih, bhh, Wfc, bfc, out);
}